// round 11
// baseline (speedup 1.0000x reference)
#include <cuda_runtime.h>
#include <math.h>

#define NPIX  (512*1024)
#define NB    8
#define KBINS 16
#define CBINS 4
#define NACC  (KBINS*CBINS + CBINS)   // 64 p_cl + 4 p_l = 68
#define TPB   128
#define GRID  592                     // 148 SMs * 4 blocks

__device__ float g_acc[NACC];         // zero at module load; reset by last block each run
__device__ unsigned int g_ticket;     // zero at module load; reset by last block each run

__device__ __forceinline__ float tanh_fast(float x) {
    float r;
    asm("tanh.approx.f32 %0, %1;" : "=f"(r) : "f"(x));
    return r;
}

__global__ void __launch_bounds__(TPB, 4)
nid_kernel(const float* __restrict__ cam, const float* __restrict__ lab,
           float* __restrict__ out)
{
    float acc_cl[KBINS * CBINS];
    float acc_l[CBINS];
#pragma unroll
    for (int i = 0; i < KBINS * CBINS; i++) acc_cl[i] = 0.0f;
#pragma unroll
    for (int c = 0; c < CBINS; c++) acc_l[c] = 0.0f;

    const int stride = GRID * TPB;
#pragma unroll 1
    for (int n = blockIdx.x * TPB + threadIdx.x; n < NPIX; n += stride) {
        // T[k] = sum_b tanh(100*gray_b - 6.25*k): camera edge sigmoids (halved
        // arg; sigmoid's +1 and *0.5 cancel in differences / normalization).
        float T[KBINS + 1];
#pragma unroll
        for (int k = 0; k <= KBINS; k++) T[k] = 0.0f;

        // label bin mass: integer counts packed 4x8-bit + rare fractional part
        unsigned int cnt = 0u;
        float PlF[CBINS];
#pragma unroll
        for (int c = 0; c < CBINS; c++) PlF[c] = 0.0f;

#pragma unroll
        for (int b = 0; b < NB; b++) {
            // ---- camera: 17 edge tanh values (independent MUFU stream) ----
            const float* cb = cam + (size_t)b * 3 * NPIX + n;
            float a = (cb[0] + cb[NPIX] + cb[2 * NPIX]) * (100.0f / 3.0f);
#pragma unroll
            for (int k = 0; k <= KBINS; k++)
                T[k] += tanh_fast(fmaf(-6.25f, (float)k, a));

            // ---- label: soft-argmax bin mass ----
            const float* lbp = lab + (size_t)b * 4 * NPIX + n;
            float l0 = lbp[0];
            float l1 = lbp[NPIX];
            float l2 = lbp[2 * NPIX];
            float l3 = lbp[3 * NPIX];
            float mx01 = fmaxf(l0, l1), mx23 = fmaxf(l2, l3);
            float mn01 = fminf(l0, l1), mn23 = fminf(l2, l3);
            float m = fmaxf(mx01, mx23);
            float second = (mx01 >= mx23) ? fmaxf(mx23, mn01) : fmaxf(mx01, mn23);

            // Fast path: gap > 0.006 => in fp32 the reference puts EXACTLY one
            // unit of mass in bin argmax (labv within 0.45 of argmax index, so
            // every 1000x edge sigmoid saturates to exact 0/1).
            if (__all_sync(0xffffffffu, (m - second) > 0.006f)) {
                int j = (l1 == m) ? 1 : 0;
                j = (l2 == m) ? 2 : j;
                j = (l3 == m) ? 3 : j;
                cnt += 1u << (j << 3);
            } else {
                // exact reference formula (matches R4 code: rel_err ~1e-6)
                float e0 = __expf((l0 - m) * 500.0f);
                float e1 = __expf((l1 - m) * 500.0f);
                float e2 = __expf((l2 - m) * 500.0f);
                float e3 = __expf((l3 - m) * 500.0f);
                float es = e0 + e1 + e2 + e3;   // >= 1
                float labv = __fdividef(fmaf(3.0f, e3, fmaf(2.0f, e2, e1)), es);
                float u  = labv + 0.5f;
                float ce = rintf(u);
                float x  = (u - ce) * 500.0f;               // tanh half-arg
                float sg = fmaf(0.5f, tanh_fast(x), 0.5f);  // sigmoid value
                int   ic = (int)ce;
#pragma unroll
                for (int c = 0; c < CBINS; c++) {
                    float addv = (ic == c) ? sg
                               : ((ic == c + 1) ? (1.0f - sg) : 0.0f);
                    PlF[c] += addv;
                }
            }
        }

        // assemble per-pixel label masses: integer counts + fractional part
        float PlS[CBINS];
#pragma unroll
        for (int c = 0; c < CBINS; c++)
            PlS[c] = PlF[c] + (float)((cnt >> (c << 3)) & 0xffu);

        // Pc[k] ~ (T[k] - T[k+1]); x0.5 cancels under normalization
#pragma unroll
        for (int k = 0; k < KBINS; k++) {
            float pc = T[k] - T[k + 1];
#pragma unroll
            for (int c = 0; c < CBINS; c++)
                acc_cl[k * CBINS + c] = fmaf(pc, PlS[c], acc_cl[k * CBINS + c]);
        }
#pragma unroll
        for (int c = 0; c < CBINS; c++) acc_l[c] += PlS[c];
    }

    // ---- block reduction: warp shuffle -> shared -> global atomics ----
    __shared__ float red[TPB / 32][NACC];
    unsigned lane = threadIdx.x & 31u;
    unsigned wrp  = threadIdx.x >> 5;

#pragma unroll
    for (int i = 0; i < KBINS * CBINS; i++) {
        float v = acc_cl[i];
        v += __shfl_down_sync(0xffffffffu, v, 16);
        v += __shfl_down_sync(0xffffffffu, v, 8);
        v += __shfl_down_sync(0xffffffffu, v, 4);
        v += __shfl_down_sync(0xffffffffu, v, 2);
        v += __shfl_down_sync(0xffffffffu, v, 1);
        if (lane == 0) red[wrp][i] = v;
    }
#pragma unroll
    for (int c = 0; c < CBINS; c++) {
        float v = acc_l[c];
        v += __shfl_down_sync(0xffffffffu, v, 16);
        v += __shfl_down_sync(0xffffffffu, v, 8);
        v += __shfl_down_sync(0xffffffffu, v, 4);
        v += __shfl_down_sync(0xffffffffu, v, 2);
        v += __shfl_down_sync(0xffffffffu, v, 1);
        if (lane == 0) red[wrp][KBINS * CBINS + c] = v;
    }
    __syncthreads();
    if (threadIdx.x < NACC) {
        float s = red[0][threadIdx.x] + red[1][threadIdx.x]
                + red[2][threadIdx.x] + red[3][threadIdx.x];
        atomicAdd(&g_acc[threadIdx.x], s);
    }
    __threadfence();   // publish g_acc contributions before taking a ticket
    __syncthreads();

    // ---- last-block finalize ----
    __shared__ unsigned int s_ticket;
    if (threadIdx.x == 0) s_ticket = atomicAdd(&g_ticket, 1u);
    __syncthreads();
    if (s_ticket != (unsigned)(GRID - 1)) return;

    if (threadIdx.x == 0) {
        __threadfence();  // acquire: see all blocks' atomics

        float pcl[KBINS * CBINS];
        float pl[CBINS];
        float scl = 0.0f, sl = 0.0f;
#pragma unroll
        for (int i = 0; i < KBINS * CBINS; i++) { pcl[i] = g_acc[i]; scl += pcl[i]; }
#pragma unroll
        for (int c = 0; c < CBINS; c++) { pl[c] = g_acc[KBINS * CBINS + c]; sl += pl[c]; }

        float inv_scl = 1.0f / scl;
        float inv_sl  = 1.0f / sl;

        float pc[KBINS];
#pragma unroll
        for (int k = 0; k < KBINS; k++) {
            float s = pcl[k * 4 + 0] + pcl[k * 4 + 1] + pcl[k * 4 + 2] + pcl[k * 4 + 3];
            pc[k] = s * inv_scl;   // row-marginal == normalized p_c
        }
#pragma unroll
        for (int c = 0; c < CBINS; c++) pl[c] *= inv_sl;

        float I = 0.0f, H = 0.0f;
#pragma unroll
        for (int k = 0; k < KBINS; k++) {
#pragma unroll
            for (int c = 0; c < CBINS; c++) {
                float p  = pcl[k * CBINS + c] * inv_scl;
                float lp = logf(p + 1e-7f);
                float lo = logf(pc[k] * pl[c] + 1e-7f);
                H -= p * lp;
                I += p * (lp - lo);
            }
        }
        float nid = 1.0f - I / H;
        out[0] = (nid - 0.95f) * 20.0f;

        // reset for next graph replay (deterministic across launches)
#pragma unroll
        for (int i = 0; i < NACC; i++) g_acc[i] = 0.0f;
        __threadfence();
        atomicExch(&g_ticket, 0u);
    }
}

extern "C" void kernel_launch(void* const* d_in, const int* in_sizes, int n_in,
                              void* d_out, int out_size)
{
    const float* cam = (const float*)d_in[0];   // (8,3,512,1024) fp32
    const float* lab = (const float*)d_in[1];   // (8,4,512,1024) fp32
    float* out = (float*)d_out;

    nid_kernel<<<GRID, TPB>>>(cam, lab, out);
}

// round 13
// speedup vs baseline: 1.2061x; 1.2061x over previous
#include <cuda_runtime.h>
#include <math.h>

#define NPIX  (512*1024)
#define HPIX  (NPIX/2)
#define NB    8
#define KBINS 16
#define CBINS 4
#define NACC  (KBINS*CBINS + CBINS)   // 64 p_cl + 4 p_l = 68
#define TPB   128
#define BPSM  3
#define GRID  (148 * BPSM)            // one wave, <=170 regs

__device__ float g_acc[NACC];         // zero at module load; reset by last block each run
__device__ unsigned int g_ticket;     // zero at module load; reset by last block each run

__device__ __forceinline__ float tanh_fast(float x) {
    float r;
    asm("tanh.approx.f32 %0, %1;" : "=f"(r) : "f"(x));
    return r;
}

__global__ void __launch_bounds__(TPB, BPSM)
nid_kernel(const float* __restrict__ cam, const float* __restrict__ lab,
           float* __restrict__ out)
{
    const float2* __restrict__ cam2 = (const float2*)cam;
    const float2* __restrict__ lab2 = (const float2*)lab;

    float acc_cl[KBINS * CBINS];
    float acc_l[CBINS];
#pragma unroll
    for (int i = 0; i < KBINS * CBINS; i++) acc_cl[i] = 0.0f;
#pragma unroll
    for (int c = 0; c < CBINS; c++) acc_l[c] = 0.0f;

    const int stride = GRID * TPB;
#pragma unroll 1
    for (int t = blockIdx.x * TPB + threadIdx.x; t < HPIX; t += stride) {
        // Pixel pair (2t, 2t+1): two independent chains A (.x) and B (.y).
        // T[k] = sum_b tanh(100*gray_b - 6.25*k); sigmoid's +1 and *0.5 cancel
        // in differences / normalization.
        float TA[KBINS + 1], TB[KBINS + 1];
        float PlA[CBINS], PlB[CBINS];
#pragma unroll
        for (int k = 0; k <= KBINS; k++) { TA[k] = 0.0f; TB[k] = 0.0f; }
#pragma unroll
        for (int c = 0; c < CBINS; c++) { PlA[c] = 0.0f; PlB[c] = 0.0f; }

#pragma unroll
        for (int b = 0; b < NB; b++) {
            // ---- camera gray (scaled): a = 100 * mean(rgb) ----
            const float2* cb = cam2 + (size_t)b * 3 * HPIX + t;
            float2 r = cb[0];
            float2 g = cb[HPIX];
            float2 bl = cb[2 * HPIX];
            float aA = (r.x + g.x + bl.x) * (100.0f / 3.0f);
            float aB = (r.y + g.y + bl.y) * (100.0f / 3.0f);

            // ---- label loads ----
            const float2* lbp = lab2 + (size_t)b * 4 * HPIX + t;
            float2 v0 = lbp[0];
            float2 v1 = lbp[HPIX];
            float2 v2 = lbp[2 * HPIX];
            float2 v3 = lbp[3 * HPIX];

            // ---- softmax A (beta = 500) ----
            float mA  = fmaxf(fmaxf(v0.x, v1.x), fmaxf(v2.x, v3.x));
            float eA0 = __expf((v0.x - mA) * 500.0f);
            float eA1 = __expf((v1.x - mA) * 500.0f);
            float eA2 = __expf((v2.x - mA) * 500.0f);
            float eA3 = __expf((v3.x - mA) * 500.0f);
            float esA = eA0 + eA1 + eA2 + eA3;   // >= 1, +1e-12 is an fp32 no-op
            float lvA = __fdividef(fmaf(3.0f, eA3, fmaf(2.0f, eA2, eA1)), esA);

            // ---- softmax B ----
            float mB  = fmaxf(fmaxf(v0.y, v1.y), fmaxf(v2.y, v3.y));
            float eB0 = __expf((v0.y - mB) * 500.0f);
            float eB1 = __expf((v1.y - mB) * 500.0f);
            float eB2 = __expf((v2.y - mB) * 500.0f);
            float eB3 = __expf((v3.y - mB) * 500.0f);
            float esB = eB0 + eB1 + eB2 + eB3;
            float lvB = __fdividef(fmaf(3.0f, eB3, fmaf(2.0f, eB2, eB1)), esB);

            // ---- label-edge sigmoid (single non-saturated edge), A ----
            float uA  = lvA + 0.5f;
            float ceA = rintf(uA);
            float sgA = fmaf(0.5f, tanh_fast((uA - ceA) * 500.0f), 0.5f);
            int   icA = (int)ceA;
            // ---- B ----
            float uB  = lvB + 0.5f;
            float ceB = rintf(uB);
            float sgB = fmaf(0.5f, tanh_fast((uB - ceB) * 500.0f), 0.5f);
            int   icB = (int)ceB;
#pragma unroll
            for (int c = 0; c < CBINS; c++) {
                float addA = (icA == c) ? sgA : ((icA == c + 1) ? (1.0f - sgA) : 0.0f);
                float addB = (icB == c) ? sgB : ((icB == c + 1) ? (1.0f - sgB) : 0.0f);
                PlA[c] += addA;
                PlB[c] += addB;
            }

            // ---- camera: 17 edge tanh per pixel, two independent streams ----
#pragma unroll
            for (int k = 0; k <= KBINS; k++) {
                float e = -6.25f * (float)k;
                TA[k] += tanh_fast(aA + e);
                TB[k] += tanh_fast(aB + e);
            }
        }

        // Pc[k] ~ (T[k] - T[k+1]); x0.5 cancels under normalization
#pragma unroll
        for (int k = 0; k < KBINS; k++) {
            float pcA = TA[k] - TA[k + 1];
            float pcB = TB[k] - TB[k + 1];
#pragma unroll
            for (int c = 0; c < CBINS; c++) {
                float v = acc_cl[k * CBINS + c];
                v = fmaf(pcA, PlA[c], v);
                v = fmaf(pcB, PlB[c], v);
                acc_cl[k * CBINS + c] = v;
            }
        }
#pragma unroll
        for (int c = 0; c < CBINS; c++) acc_l[c] += PlA[c] + PlB[c];
    }

    // ---- block reduction: warp shuffle -> shared -> global atomics ----
    __shared__ float red[TPB / 32][NACC];
    unsigned lane = threadIdx.x & 31u;
    unsigned wrp  = threadIdx.x >> 5;

#pragma unroll
    for (int i = 0; i < KBINS * CBINS; i++) {
        float v = acc_cl[i];
        v += __shfl_down_sync(0xffffffffu, v, 16);
        v += __shfl_down_sync(0xffffffffu, v, 8);
        v += __shfl_down_sync(0xffffffffu, v, 4);
        v += __shfl_down_sync(0xffffffffu, v, 2);
        v += __shfl_down_sync(0xffffffffu, v, 1);
        if (lane == 0) red[wrp][i] = v;
    }
#pragma unroll
    for (int c = 0; c < CBINS; c++) {
        float v = acc_l[c];
        v += __shfl_down_sync(0xffffffffu, v, 16);
        v += __shfl_down_sync(0xffffffffu, v, 8);
        v += __shfl_down_sync(0xffffffffu, v, 4);
        v += __shfl_down_sync(0xffffffffu, v, 2);
        v += __shfl_down_sync(0xffffffffu, v, 1);
        if (lane == 0) red[wrp][KBINS * CBINS + c] = v;
    }
    __syncthreads();
    if (threadIdx.x < NACC) {
        float s = red[0][threadIdx.x] + red[1][threadIdx.x]
                + red[2][threadIdx.x] + red[3][threadIdx.x];
        atomicAdd(&g_acc[threadIdx.x], s);
    }
    __threadfence();   // publish g_acc contributions before taking a ticket
    __syncthreads();

    // ---- last-block finalize ----
    __shared__ unsigned int s_ticket;
    if (threadIdx.x == 0) s_ticket = atomicAdd(&g_ticket, 1u);
    __syncthreads();
    if (s_ticket != (unsigned)(GRID - 1)) return;

    if (threadIdx.x == 0) {
        __threadfence();  // acquire: see all blocks' atomics

        float pcl[KBINS * CBINS];
        float pl[CBINS];
        float scl = 0.0f, sl = 0.0f;
#pragma unroll
        for (int i = 0; i < KBINS * CBINS; i++) { pcl[i] = g_acc[i]; scl += pcl[i]; }
#pragma unroll
        for (int c = 0; c < CBINS; c++) { pl[c] = g_acc[KBINS * CBINS + c]; sl += pl[c]; }

        float inv_scl = 1.0f / scl;
        float inv_sl  = 1.0f / sl;

        float pc[KBINS];
#pragma unroll
        for (int k = 0; k < KBINS; k++) {
            float s = pcl[k * 4 + 0] + pcl[k * 4 + 1] + pcl[k * 4 + 2] + pcl[k * 4 + 3];
            pc[k] = s * inv_scl;   // row-marginal == normalized p_c
        }
#pragma unroll
        for (int c = 0; c < CBINS; c++) pl[c] *= inv_sl;

        float I = 0.0f, H = 0.0f;
#pragma unroll
        for (int k = 0; k < KBINS; k++) {
#pragma unroll
            for (int c = 0; c < CBINS; c++) {
                float p  = pcl[k * CBINS + c] * inv_scl;
                float lp = logf(p + 1e-7f);
                float lo = logf(pc[k] * pl[c] + 1e-7f);
                H -= p * lp;
                I += p * (lp - lo);
            }
        }
        float nid = 1.0f - I / H;
        out[0] = (nid - 0.95f) * 20.0f;

        // reset for next graph replay (deterministic across launches)
#pragma unroll
        for (int i = 0; i < NACC; i++) g_acc[i] = 0.0f;
        __threadfence();
        atomicExch(&g_ticket, 0u);
    }
}

extern "C" void kernel_launch(void* const* d_in, const int* in_sizes, int n_in,
                              void* d_out, int out_size)
{
    const float* cam = (const float*)d_in[0];   // (8,3,512,1024) fp32
    const float* lab = (const float*)d_in[1];   // (8,4,512,1024) fp32
    float* out = (float*)d_out;

    nid_kernel<<<GRID, TPB>>>(cam, lab, out);
}

// round 14
// speedup vs baseline: 1.3100x; 1.0862x over previous
#include <cuda_runtime.h>
#include <math.h>

#define NPIX  (512*1024)
#define NB    8
#define KBINS 16
#define CBINS 4
#define NACC  (KBINS*CBINS + CBINS)   // 64 p_cl + 4 p_l = 68
#define TPB   128
#define GRID  592                     // 148 SMs * 4 blocks, one wave

__device__ float g_acc[NACC];         // zero at module load; reset by last block each run
__device__ unsigned int g_ticket;     // zero at module load; reset by last block each run

__device__ __forceinline__ float tanh_fast(float x) {
    float r;
    asm("tanh.approx.f32 %0, %1;" : "=f"(r) : "f"(x));
    return r;
}

__global__ void __launch_bounds__(TPB, 4)
nid_kernel(const float* __restrict__ cam, const float* __restrict__ lab,
           float* __restrict__ out)
{
    // per-thread 16-bin camera histogram, stride 17 (tid*17 mod 32 bijective -> conflict-light)
    __shared__ float pcs[TPB * 17];
    float* __restrict__ myPc = &pcs[threadIdx.x * 17];

    float acc_cl[KBINS * CBINS];
    float acc_l[CBINS];
#pragma unroll
    for (int i = 0; i < KBINS * CBINS; i++) acc_cl[i] = 0.0f;
#pragma unroll
    for (int c = 0; c < CBINS; c++) acc_l[c] = 0.0f;

    const int stride = GRID * TPB;
#pragma unroll 1
    for (int n = blockIdx.x * TPB + threadIdx.x; n < NPIX; n += stride) {
        float PlS[CBINS];
#pragma unroll
        for (int c = 0; c < CBINS; c++) PlS[c] = 0.0f;
#pragma unroll
        for (int k = 0; k < KBINS; k++) myPc[k] = 0.0f;

#pragma unroll
        for (int b = 0; b < NB; b++) {
            // ---- camera: g16 = 16*gray; only edges ie-1..ie+2 non-saturated.
            // w_j = tanh(6.25*(fr+1-j)); tanh-scale masses (x0.5 cancels later):
            // bin ie-2: 1-w0, ie-1: w0-w1, ie: w1-w2, ie+1: w2-w3.
            const float* cb = cam + (size_t)b * 3 * NPIX + n;
            float g16 = (cb[0] + cb[NPIX] + cb[2 * NPIX]) * (16.0f / 3.0f);
            float ef  = floorf(g16);
            float fr  = g16 - ef;
            int   ie  = (int)ef;
            float w0 = tanh_fast(fmaf(6.25f, fr,   6.25f));
            float w1 = tanh_fast(6.25f * fr);
            float w2 = tanh_fast(fmaf(6.25f, fr,  -6.25f));
            float w3 = tanh_fast(fmaf(6.25f, fr, -12.5f));
            float m0 = 1.0f - w0;
            float m1 = w0 - w1;
            float m2 = w1 - w2;
            float m3 = w2 - w3;
            int base = ie - 2;
            if ((unsigned)(base + 0) < 16u) myPc[base + 0] += m0;
            if ((unsigned)(base + 1) < 16u) myPc[base + 1] += m1;
            if ((unsigned)(base + 2) < 16u) myPc[base + 2] += m2;
            if ((unsigned)(base + 3) < 16u) myPc[base + 3] += m3;

            // ---- label soft-argmax (beta = 500), exact R4 path ----
            const float* lbp = lab + (size_t)b * 4 * NPIX + n;
            float l0 = lbp[0];
            float l1 = lbp[NPIX];
            float l2 = lbp[2 * NPIX];
            float l3 = lbp[3 * NPIX];
            float m  = fmaxf(fmaxf(l0, l1), fmaxf(l2, l3));
            float e0 = __expf((l0 - m) * 500.0f);
            float e1 = __expf((l1 - m) * 500.0f);
            float e2 = __expf((l2 - m) * 500.0f);
            float e3 = __expf((l3 - m) * 500.0f);
            float es = e0 + e1 + e2 + e3;   // >= 1, +1e-12 is an fp32 no-op
            float labv = __fdividef(fmaf(3.0f, e3, fmaf(2.0f, e2, e1)), es);

            // single non-saturated label-edge sigmoid
            float u  = labv + 0.5f;
            float ce = rintf(u);
            float x  = (u - ce) * 500.0f;               // tanh half-arg
            float sg = fmaf(0.5f, tanh_fast(x), 0.5f);
            int   ic = (int)ce;
#pragma unroll
            for (int c = 0; c < CBINS; c++) {
                float addv = (ic == c) ? sg : ((ic == c + 1) ? (1.0f - sg) : 0.0f);
                PlS[c] += addv;
            }
        }

        // readback + outer product: acc_cl[k][c] += Pc[k] * PlS[c]
#pragma unroll
        for (int k = 0; k < KBINS; k++) {
            float pck = myPc[k];
#pragma unroll
            for (int c = 0; c < CBINS; c++)
                acc_cl[k * CBINS + c] = fmaf(pck, PlS[c], acc_cl[k * CBINS + c]);
        }
#pragma unroll
        for (int c = 0; c < CBINS; c++) acc_l[c] += PlS[c];
    }

    // ---- block reduction: warp shuffle -> shared -> global atomics ----
    __syncthreads();   // done with pcs; reuse barrier before red[] writes
    __shared__ float red[TPB / 32][NACC];
    unsigned lane = threadIdx.x & 31u;
    unsigned wrp  = threadIdx.x >> 5;

#pragma unroll
    for (int i = 0; i < KBINS * CBINS; i++) {
        float v = acc_cl[i];
        v += __shfl_down_sync(0xffffffffu, v, 16);
        v += __shfl_down_sync(0xffffffffu, v, 8);
        v += __shfl_down_sync(0xffffffffu, v, 4);
        v += __shfl_down_sync(0xffffffffu, v, 2);
        v += __shfl_down_sync(0xffffffffu, v, 1);
        if (lane == 0) red[wrp][i] = v;
    }
#pragma unroll
    for (int c = 0; c < CBINS; c++) {
        float v = acc_l[c];
        v += __shfl_down_sync(0xffffffffu, v, 16);
        v += __shfl_down_sync(0xffffffffu, v, 8);
        v += __shfl_down_sync(0xffffffffu, v, 4);
        v += __shfl_down_sync(0xffffffffu, v, 2);
        v += __shfl_down_sync(0xffffffffu, v, 1);
        if (lane == 0) red[wrp][KBINS * CBINS + c] = v;
    }
    __syncthreads();
    if (threadIdx.x < NACC) {
        float s = red[0][threadIdx.x] + red[1][threadIdx.x]
                + red[2][threadIdx.x] + red[3][threadIdx.x];
        atomicAdd(&g_acc[threadIdx.x], s);
    }
    __threadfence();   // publish g_acc contributions before taking a ticket
    __syncthreads();

    // ---- last-block finalize ----
    __shared__ unsigned int s_ticket;
    if (threadIdx.x == 0) s_ticket = atomicAdd(&g_ticket, 1u);
    __syncthreads();
    if (s_ticket != (unsigned)(GRID - 1)) return;

    if (threadIdx.x == 0) {
        __threadfence();  // acquire: see all blocks' atomics

        float pcl[KBINS * CBINS];
        float pl[CBINS];
        float scl = 0.0f, sl = 0.0f;
#pragma unroll
        for (int i = 0; i < KBINS * CBINS; i++) { pcl[i] = g_acc[i]; scl += pcl[i]; }
#pragma unroll
        for (int c = 0; c < CBINS; c++) { pl[c] = g_acc[KBINS * CBINS + c]; sl += pl[c]; }

        float inv_scl = 1.0f / scl;
        float inv_sl  = 1.0f / sl;

        float pc[KBINS];
#pragma unroll
        for (int k = 0; k < KBINS; k++) {
            float s = pcl[k * 4 + 0] + pcl[k * 4 + 1] + pcl[k * 4 + 2] + pcl[k * 4 + 3];
            pc[k] = s * inv_scl;   // row-marginal == normalized p_c
        }
#pragma unroll
        for (int c = 0; c < CBINS; c++) pl[c] *= inv_sl;

        float I = 0.0f, H = 0.0f;
#pragma unroll
        for (int k = 0; k < KBINS; k++) {
#pragma unroll
            for (int c = 0; c < CBINS; c++) {
                float p  = pcl[k * CBINS + c] * inv_scl;
                float lp = logf(p + 1e-7f);
                float lo = logf(pc[k] * pl[c] + 1e-7f);
                H -= p * lp;
                I += p * (lp - lo);
            }
        }
        float nid = 1.0f - I / H;
        out[0] = (nid - 0.95f) * 20.0f;

        // reset for next graph replay (deterministic across launches)
#pragma unroll
        for (int i = 0; i < NACC; i++) g_acc[i] = 0.0f;
        __threadfence();
        atomicExch(&g_ticket, 0u);
    }
}

extern "C" void kernel_launch(void* const* d_in, const int* in_sizes, int n_in,
                              void* d_out, int out_size)
{
    const float* cam = (const float*)d_in[0];   // (8,3,512,1024) fp32
    const float* lab = (const float*)d_in[1];   // (8,4,512,1024) fp32
    float* out = (float*)d_out;

    nid_kernel<<<GRID, TPB>>>(cam, lab, out);
}